// round 1
// baseline (speedup 1.0000x reference)
#include <cuda_runtime.h>
#include <math.h>

// ---------------------------------------------------------------------------
// PointSwinBlock: x += W-MSA(LN1(x)); x += MLP(LN2(x))
// B=2, N=65536, DIM=256, HEADS=8, HEAD_DIM=32, WS=64, MLP=1024
// Round 0: fp32 baseline. Tiled SGEMM (128x128x16, 8x8/thread), fused
// epilogues, shifted-window attention via modular index gather.
// ---------------------------------------------------------------------------

#define DIMC   256
#define NTOK   131072          // 2 * 65536
#define NPB    65536           // tokens per batch
#define HEADS  8
#define HDIM   32
#define WS     64
#define MLPD   1024

// scratch (allocation-free: __device__ globals)
__device__ float g_ln  [(size_t)NTOK * DIMC];   // 134 MB
__device__ float g_qkv [(size_t)NTOK * 768];    // 402 MB
__device__ float g_attn[(size_t)NTOK * DIMC];   // 134 MB
__device__ float g_h   [(size_t)NTOK * MLPD];   // 537 MB

// ---------------------------------------------------------------------------
// LayerNorm: one block per row, 256 threads (DIM=256)
// ---------------------------------------------------------------------------
__global__ void ln_kernel(const float* __restrict__ x,
                          const float* __restrict__ g,
                          const float* __restrict__ b,
                          float* __restrict__ y)
{
    long row = blockIdx.x;
    int  t   = threadIdx.x;
    float v  = x[row * DIMC + t];
    float s  = v, s2 = v * v;
    #pragma unroll
    for (int o = 16; o; o >>= 1) {
        s  += __shfl_xor_sync(0xffffffffu, s,  o);
        s2 += __shfl_xor_sync(0xffffffffu, s2, o);
    }
    __shared__ float ss[8], ss2[8];
    int w = t >> 5, l = t & 31;
    if (l == 0) { ss[w] = s; ss2[w] = s2; }
    __syncthreads();
    if (t < 32) {
        float a  = (l < 8) ? ss[l]  : 0.f;
        float a2 = (l < 8) ? ss2[l] : 0.f;
        #pragma unroll
        for (int o = 4; o; o >>= 1) {
            a  += __shfl_xor_sync(0xffffffffu, a,  o);
            a2 += __shfl_xor_sync(0xffffffffu, a2, o);
        }
        if (l == 0) { ss[0] = a; ss2[0] = a2; }
    }
    __syncthreads();
    float mu  = ss[0]  * (1.f / DIMC);
    float var = ss2[0] * (1.f / DIMC) - mu * mu;
    float inv = rsqrtf(var + 1e-5f);
    y[row * DIMC + t] = (v - mu) * inv * g[t] + b[t];
}

// ---------------------------------------------------------------------------
// SGEMM: C[M,N] = A[M,K] @ B[K,N] with epilogue.
// 128x128 block tile, BK=16, 256 threads, 8x8 per thread.
// ---------------------------------------------------------------------------
#define BM 128
#define BN 128
#define BK 16
#define TM 8
#define TN 8

#define EPI_NONE      0
#define EPI_BIAS_RES  1   // C = acc + bias[col] + res[row,col]
#define EPI_GELU_BIAS 2   // C = gelu(acc + bias[col])
#define EPI_BIAS_ACC  3   // C = C + acc + bias[col]

__device__ __forceinline__ float gelu_exact(float v)
{
    return 0.5f * v * (1.f + erff(v * 0.7071067811865476f));
}

template <int EPI>
__global__ __launch_bounds__(256, 2)
void sgemm_kernel(const float* __restrict__ A, const float* __restrict__ B,
                  float* __restrict__ C,
                  const float* __restrict__ bias,
                  const float* __restrict__ res,
                  int M, int N, int K)
{
    __shared__ float As[BK][BM];
    __shared__ float Bs[BK][BN];

    int  tid   = threadIdx.x;
    int  tx    = tid & 15;          // 0..15 -> N
    int  ty    = tid >> 4;          // 0..15 -> M
    long cRow0 = (long)blockIdx.y * BM;
    long cCol0 = (long)blockIdx.x * BN;

    const float* Ab = A + cRow0 * K;
    const float* Bb = B + cCol0;

    float acc[TM][TN];
    #pragma unroll
    for (int i = 0; i < TM; i++)
        #pragma unroll
        for (int j = 0; j < TN; j++) acc[i][j] = 0.f;

    for (int k0 = 0; k0 < K; k0 += BK) {
        // load A tile (BM x BK) transposed, B tile (BK x BN)
        #pragma unroll
        for (int it = 0; it < 2; it++) {
            int slot = tid + it * 256;
            int arow = slot >> 2, ac4 = slot & 3;
            float4 av = *reinterpret_cast<const float4*>(
                Ab + (long)arow * K + k0 + ac4 * 4);
            As[ac4 * 4 + 0][arow] = av.x;
            As[ac4 * 4 + 1][arow] = av.y;
            As[ac4 * 4 + 2][arow] = av.z;
            As[ac4 * 4 + 3][arow] = av.w;

            int brow = slot >> 5, bc4 = slot & 31;
            float4 bv = *reinterpret_cast<const float4*>(
                Bb + (long)(k0 + brow) * N + bc4 * 4);
            *reinterpret_cast<float4*>(&Bs[brow][bc4 * 4]) = bv;
        }
        __syncthreads();

        #pragma unroll
        for (int kk = 0; kk < BK; kk++) {
            float a[TM], b[TN];
            *reinterpret_cast<float4*>(&a[0]) =
                *reinterpret_cast<const float4*>(&As[kk][ty * TM]);
            *reinterpret_cast<float4*>(&a[4]) =
                *reinterpret_cast<const float4*>(&As[kk][ty * TM + 4]);
            *reinterpret_cast<float4*>(&b[0]) =
                *reinterpret_cast<const float4*>(&Bs[kk][tx * TN]);
            *reinterpret_cast<float4*>(&b[4]) =
                *reinterpret_cast<const float4*>(&Bs[kk][tx * TN + 4]);
            #pragma unroll
            for (int i = 0; i < TM; i++)
                #pragma unroll
                for (int j = 0; j < TN; j++)
                    acc[i][j] = fmaf(a[i], b[j], acc[i][j]);
        }
        __syncthreads();
    }

    // epilogue
    #pragma unroll
    for (int i = 0; i < TM; i++) {
        long row = cRow0 + ty * TM + i;
        float* crow = C + row * (long)N;
        const float* rrow = (EPI == EPI_BIAS_RES) ? (res + row * (long)N) : nullptr;
        #pragma unroll
        for (int j = 0; j < TN; j += 4) {
            int col = (int)cCol0 + tx * TN + j;
            float4 v;
            v.x = acc[i][j + 0];
            v.y = acc[i][j + 1];
            v.z = acc[i][j + 2];
            v.w = acc[i][j + 3];
            if (EPI == EPI_BIAS_RES) {
                v.x += bias[col + 0] + rrow[col + 0];
                v.y += bias[col + 1] + rrow[col + 1];
                v.z += bias[col + 2] + rrow[col + 2];
                v.w += bias[col + 3] + rrow[col + 3];
            } else if (EPI == EPI_GELU_BIAS) {
                v.x = gelu_exact(v.x + bias[col + 0]);
                v.y = gelu_exact(v.y + bias[col + 1]);
                v.z = gelu_exact(v.z + bias[col + 2]);
                v.w = gelu_exact(v.w + bias[col + 3]);
            } else if (EPI == EPI_BIAS_ACC) {
                float4 c = *reinterpret_cast<const float4*>(&crow[col]);
                v.x += bias[col + 0] + c.x;
                v.y += bias[col + 1] + c.y;
                v.z += bias[col + 2] + c.z;
                v.w += bias[col + 3] + c.w;
            }
            *reinterpret_cast<float4*>(&crow[col]) = v;
        }
    }
}

// ---------------------------------------------------------------------------
// Shifted-window attention: one block per (window, head, batch).
// Window w, local pos j -> original token (w*64 + 32 + j) mod 65536.
// qkv row layout: [3][HEADS][HDIM] (q at s=0, k at s=1, v at s=2).
// ---------------------------------------------------------------------------
__global__ __launch_bounds__(256)
void attn_kernel(const float* __restrict__ qkv,
                 const float* __restrict__ pos,
                 float* __restrict__ out)
{
    int w   = blockIdx.x;
    int h   = blockIdx.y;
    int b   = blockIdx.z;
    int tid = threadIdx.x;

    __shared__ float q[WS][HDIM], k[WS][HDIM], v[WS][HDIM];
    __shared__ float dots[WS][WS + 1];

    // load q,k,v (each 64x32 floats) with shifted gather
    #pragma unroll
    for (int it = 0; it < 2; it++) {
        int slot = tid + it * 256;           // 512 slots = 64 rows x 8 float4
        int row  = slot >> 3, c4 = slot & 7;
        long t = (long)b * NPB + ((w * WS + WS / 2 + row) & (NPB - 1));
        const float* base = qkv + t * 768 + h * HDIM + c4 * 4;
        *reinterpret_cast<float4*>(&q[row][c4 * 4]) =
            *reinterpret_cast<const float4*>(base);
        *reinterpret_cast<float4*>(&k[row][c4 * 4]) =
            *reinterpret_cast<const float4*>(base + 256);
        *reinterpret_cast<float4*>(&v[row][c4 * 4]) =
            *reinterpret_cast<const float4*>(base + 512);
    }
    __syncthreads();

    const float scale = 0.17677669529663687f;   // 32^-0.5
    #pragma unroll
    for (int it = 0; it < 16; it++) {
        int e = tid + it * 256;
        int i = e >> 6, j = e & 63;
        float s = 0.f;
        #pragma unroll
        for (int d = 0; d < HDIM; d++) s = fmaf(q[i][d], k[j][d], s);
        dots[i][j] = s * scale + pos[i * WS + j];
    }
    __syncthreads();

    if (tid < WS) {
        float m = -INFINITY;
        #pragma unroll 8
        for (int j = 0; j < WS; j++) m = fmaxf(m, dots[tid][j]);
        float sum = 0.f;
        #pragma unroll 8
        for (int j = 0; j < WS; j++) {
            float e = expf(dots[tid][j] - m);
            dots[tid][j] = e;
            sum += e;
        }
        float inv = 1.f / sum;
        #pragma unroll 8
        for (int j = 0; j < WS; j++) dots[tid][j] *= inv;
    }
    __syncthreads();

    #pragma unroll
    for (int it = 0; it < 8; it++) {
        int e = tid + it * 256;                 // 2048 = 64 rows x 32 dims
        int i = e >> 5, d = e & 31;
        float s = 0.f;
        #pragma unroll
        for (int j = 0; j < WS; j++) s = fmaf(dots[i][j], v[j][d], s);
        long t = (long)b * NPB + ((w * WS + WS / 2 + i) & (NPB - 1));
        out[t * DIMC + h * HDIM + d] = s;
    }
}

// ---------------------------------------------------------------------------
// launch
// ---------------------------------------------------------------------------
extern "C" void kernel_launch(void* const* d_in, const int* in_sizes, int n_in,
                              void* d_out, int out_size)
{
    const float* x      = (const float*)d_in[0];
    const float* w_qkv  = (const float*)d_in[1];
    const float* w_out  = (const float*)d_in[2];
    const float* b_out  = (const float*)d_in[3];
    const float* pos    = (const float*)d_in[4];
    const float* ln1_g  = (const float*)d_in[5];
    const float* ln1_b  = (const float*)d_in[6];
    const float* w1     = (const float*)d_in[7];
    const float* b1     = (const float*)d_in[8];
    const float* w2     = (const float*)d_in[9];
    const float* b2     = (const float*)d_in[10];
    const float* ln2_g  = (const float*)d_in[11];
    const float* ln2_b  = (const float*)d_in[12];
    float* out = (float*)d_out;

    int tokens = in_sizes[0] / DIMC;     // 131072

    float *p_ln, *p_qkv, *p_attn, *p_h;
    cudaGetSymbolAddress((void**)&p_ln,   g_ln);
    cudaGetSymbolAddress((void**)&p_qkv,  g_qkv);
    cudaGetSymbolAddress((void**)&p_attn, g_attn);
    cudaGetSymbolAddress((void**)&p_h,    g_h);

    // 1) LN1
    ln_kernel<<<tokens, 256>>>(x, ln1_g, ln1_b, p_ln);

    // 2) QKV = LN1(x) @ w_qkv   [131072 x 768]
    {
        dim3 grid(768 / BN, tokens / BM);
        sgemm_kernel<EPI_NONE><<<grid, 256>>>(p_ln, w_qkv, p_qkv,
                                              nullptr, nullptr,
                                              tokens, 768, DIMC);
    }

    // 3) windowed attention (shifted gather)
    {
        dim3 grid(NPB / WS, HEADS, tokens / NPB);
        attn_kernel<<<grid, 256>>>(p_qkv, pos, p_attn);
    }

    // 4) x2 = x + attn @ w_out + b_out  -> d_out
    {
        dim3 grid(DIMC / BN, tokens / BM);
        sgemm_kernel<EPI_BIAS_RES><<<grid, 256>>>(p_attn, w_out, out,
                                                  b_out, x,
                                                  tokens, DIMC, DIMC);
    }

    // 5) LN2
    ln_kernel<<<tokens, 256>>>(out, ln2_g, ln2_b, p_ln);

    // 6) h = gelu(LN2 @ w1 + b1)   [131072 x 1024]
    {
        dim3 grid(MLPD / BN, tokens / BM);
        sgemm_kernel<EPI_GELU_BIAS><<<grid, 256>>>(p_ln, w1, p_h,
                                                   b1, nullptr,
                                                   tokens, MLPD, DIMC);
    }

    // 7) out += h @ w2 + b2
    {
        dim3 grid(DIMC / BN, tokens / BM);
        sgemm_kernel<EPI_BIAS_ACC><<<grid, 256>>>(p_h, w2, out,
                                                  b2, nullptr,
                                                  tokens, DIMC, MLPD);
    }
}

// round 3
// speedup vs baseline: 1.9065x; 1.9065x over previous
#include <cuda_runtime.h>
#include <math.h>
#include <stdint.h>

// ---------------------------------------------------------------------------
// PointSwinBlock on GB300 (sm_103 non-'a' target): tf32 mma.sync GEMMs.
// B=2, N=65536, DIM=256, HEADS=8, HEAD_DIM=32, WS=64, MLP=1024
// ---------------------------------------------------------------------------

#define DIMC   256
#define NTOK   131072
#define NPB    65536
#define HEADS  8
#define HDIM   32
#define WS     64
#define MLPD   1024

// scratch (allocation-free: __device__ globals)
__device__ float g_ln  [(size_t)NTOK * DIMC];
__device__ float g_qkv [(size_t)NTOK * 768];
__device__ float g_attn[(size_t)NTOK * DIMC];
__device__ float g_h   [(size_t)NTOK * MLPD];
// transposed weights [N,K]
__device__ float g_wqkvT[768 * DIMC];
__device__ float g_woutT[DIMC * DIMC];
__device__ float g_w1T  [MLPD * DIMC];
__device__ float g_w2T  [DIMC * MLPD];

// ---------------------------------------------------------------------------
// LayerNorm: one block per row, 256 threads
// ---------------------------------------------------------------------------
__global__ void ln_kernel(const float* __restrict__ x,
                          const float* __restrict__ g,
                          const float* __restrict__ b,
                          float* __restrict__ y)
{
    long row = blockIdx.x;
    int  t   = threadIdx.x;
    float v  = x[row * DIMC + t];
    float s  = v, s2 = v * v;
    #pragma unroll
    for (int o = 16; o; o >>= 1) {
        s  += __shfl_xor_sync(0xffffffffu, s,  o);
        s2 += __shfl_xor_sync(0xffffffffu, s2, o);
    }
    __shared__ float ss[8], ss2[8];
    int w = t >> 5, l = t & 31;
    if (l == 0) { ss[w] = s; ss2[w] = s2; }
    __syncthreads();
    if (t < 32) {
        float a  = (l < 8) ? ss[l]  : 0.f;
        float a2 = (l < 8) ? ss2[l] : 0.f;
        #pragma unroll
        for (int o = 4; o; o >>= 1) {
            a  += __shfl_xor_sync(0xffffffffu, a,  o);
            a2 += __shfl_xor_sync(0xffffffffu, a2, o);
        }
        if (l == 0) { ss[0] = a; ss2[0] = a2; }
    }
    __syncthreads();
    float mu  = ss[0]  * (1.f / DIMC);
    float var = ss2[0] * (1.f / DIMC) - mu * mu;
    float inv = rsqrtf(var + 1e-5f);
    y[row * DIMC + t] = (v - mu) * inv * g[t] + b[t];
}

// ---------------------------------------------------------------------------
// Weight transpose: in[R,C] -> out[C,R]
// ---------------------------------------------------------------------------
__global__ void transpose_kernel(const float* __restrict__ in,
                                 float* __restrict__ out, int R, int C)
{
    __shared__ float t[32][33];
    int bx = blockIdx.x * 32, by = blockIdx.y * 32;
    #pragma unroll
    for (int i = threadIdx.y; i < 32; i += 8)
        t[i][threadIdx.x] = in[(long)(by + i) * C + bx + threadIdx.x];
    __syncthreads();
    #pragma unroll
    for (int i = threadIdx.y; i < 32; i += 8)
        out[(long)(bx + i) * R + by + threadIdx.x] = t[threadIdx.x][i];
}

// ---------------------------------------------------------------------------
// tf32 mma.sync GEMM: C[M,N] = A[M,K] @ Bt[N,K]^T, with epilogue.
// 128x128 block tile, BK=32 (4 k-steps of 8), 256 threads = 8 warps (2m x 4n),
// warp tile 64x32. Double-buffered smem, register-staged LDG prefetch.
// ---------------------------------------------------------------------------
#define EPI_NONE      0
#define EPI_BIAS_RES  1
#define EPI_GELU_BIAS 2
#define EPI_BIAS_ACC  3

#define BM 128
#define BN 128
#define BK 32
// smem (float units): As 2 stages * 4 ksteps * 128 rows * 8 = 8192, Bs same
#define B_OFF 8192
#define GEMM_SMEM_BYTES (16384 * 4)

__device__ __forceinline__ uint32_t f2tf32(float f) {
    uint32_t u;
    asm("cvt.rna.tf32.f32 %0, %1;" : "=r"(u) : "f"(f));
    return u;
}

__device__ __forceinline__ void mma_tf32(float* d, const uint32_t* a,
                                         const uint32_t* b) {
    asm volatile(
        "mma.sync.aligned.m16n8k8.row.col.f32.tf32.tf32.f32 "
        "{%0,%1,%2,%3}, {%4,%5,%6,%7}, {%8,%9}, {%0,%1,%2,%3};"
        : "+f"(d[0]), "+f"(d[1]), "+f"(d[2]), "+f"(d[3])
        : "r"(a[0]), "r"(a[1]), "r"(a[2]), "r"(a[3]),
          "r"(b[0]), "r"(b[1]));
}

__device__ __forceinline__ float gelu_exact(float v)
{
    return 0.5f * v * (1.f + erff(v * 0.7071067811865476f));
}

// smem element index for A: (stage, ks, row, pair, slot)
// element (row, k): ks=k>>3, c=(k&7)&3, s=(k&7)>>2, pair = c ^ ks (swizzle)
__device__ __forceinline__ int a_idx(int st, int ks, int row) {
    return ((st * 4 + ks) * 128 + row) * 8;
}

template <int EPI>
__global__ __launch_bounds__(256, 1)
void tc_gemm(const float* __restrict__ A, const float* __restrict__ Bt,
             float* __restrict__ C,
             const float* __restrict__ bias,
             const float* __restrict__ res,
             int M, int N, int K)
{
    extern __shared__ uint32_t sm[];
    int  tid    = threadIdx.x;
    int  lane   = tid & 31;
    int  wid    = tid >> 5;
    int  warp_m = wid >> 2;          // 0..1 (64 rows each)
    int  warp_n = wid & 3;           // 0..3 (32 cols each)
    long m0     = (long)blockIdx.y * BM;
    int  n0     = blockIdx.x * BN;
    int  nc     = K / BK;

    // per-thread LDG assignment: 4 float4 for A, 4 for B
    // slot = it*256 + tid; row = slot>>3 (0..127); c4 = slot&7 (k float4 idx)
    int l_row = tid >> 3;            // +32 per it
    int l_c4  = tid & 7;

    float4 aR[4], bR[4];

    auto ldg_chunk = [&](int kc) {
        const float* Ap = A  + (m0 + l_row) * K + kc * BK + l_c4 * 4;
        const float* Bp = Bt + ((long)n0 + l_row) * K + kc * BK + l_c4 * 4;
        #pragma unroll
        for (int it = 0; it < 4; it++) {
            aR[it] = *reinterpret_cast<const float4*>(Ap + (long)(it * 32) * K);
            bR[it] = *reinterpret_cast<const float4*>(Bp + (long)(it * 32) * K);
        }
    };

    auto sts_chunk = [&](int st) {
        int ks = l_c4 >> 1;
        int s  = l_c4 & 1;
        #pragma unroll
        for (int it = 0; it < 4; it++) {
            int row = l_row + it * 32;
            int ab  = a_idx(st, ks, row);
            uint32_t* pa = &sm[ab];
            uint32_t* pb = &sm[B_OFF + ab];
            const float* av = &aR[it].x;
            const float* bv = &bR[it].x;
            #pragma unroll
            for (int e = 0; e < 4; e++) {
                int pp = e ^ ks;
                pa[pp * 2 + s] = f2tf32(av[e]);
                pb[pp * 2 + s] = f2tf32(bv[e]);
            }
        }
    };

    float acc[4][4][4];
    #pragma unroll
    for (int i = 0; i < 4; i++)
        #pragma unroll
        for (int j = 0; j < 4; j++)
            #pragma unroll
            for (int e = 0; e < 4; e++) acc[i][j][e] = 0.f;

    // pipeline prologue
    ldg_chunk(0);
    sts_chunk(0);
    if (nc > 1) ldg_chunk(1);
    __syncthreads();

    int g = lane >> 2;       // groupID
    int q = lane & 3;        // thread-in-group

    for (int c = 0; c < nc; c++) {
        int st = c & 1;
        if (c + 1 < nc) {
            sts_chunk((c + 1) & 1);
            if (c + 2 < nc) ldg_chunk(c + 2);
        }

        #pragma unroll
        for (int ks = 0; ks < 4; ks++) {
            int pp2 = ((q ^ ks) << 1);
            uint32_t af[4][4];
            #pragma unroll
            for (int mf = 0; mf < 4; mf++) {
                int row = warp_m * 64 + mf * 16 + g;
                uint2 lo = *reinterpret_cast<const uint2*>(
                    &sm[a_idx(st, ks, row) + pp2]);
                uint2 hi = *reinterpret_cast<const uint2*>(
                    &sm[a_idx(st, ks, row + 8) + pp2]);
                af[mf][0] = lo.x; af[mf][1] = hi.x;
                af[mf][2] = lo.y; af[mf][3] = hi.y;
            }
            uint32_t bf[4][2];
            #pragma unroll
            for (int nf = 0; nf < 4; nf++) {
                int col = warp_n * 32 + nf * 8 + g;
                uint2 bb = *reinterpret_cast<const uint2*>(
                    &sm[B_OFF + a_idx(st, ks, col) + pp2]);
                bf[nf][0] = bb.x; bf[nf][1] = bb.y;
            }
            #pragma unroll
            for (int mf = 0; mf < 4; mf++)
                #pragma unroll
                for (int nf = 0; nf < 4; nf++)
                    mma_tf32(acc[mf][nf], af[mf], bf[nf]);
        }
        __syncthreads();
    }

    // epilogue: C frag rows g, g+8; cols 2q, 2q+1
    float2 bv[4];
    if (EPI != EPI_NONE) {
        #pragma unroll
        for (int nf = 0; nf < 4; nf++) {
            int col = n0 + warp_n * 32 + nf * 8 + q * 2;
            bv[nf] = *reinterpret_cast<const float2*>(&bias[col]);
        }
    }

    #pragma unroll
    for (int mf = 0; mf < 4; mf++) {
        long r0 = m0 + warp_m * 64 + mf * 16 + g;
        long r1 = r0 + 8;
        #pragma unroll
        for (int nf = 0; nf < 4; nf++) {
            int col = n0 + warp_n * 32 + nf * 8 + q * 2;
            float2 v0 = make_float2(acc[mf][nf][0], acc[mf][nf][1]);
            float2 v1 = make_float2(acc[mf][nf][2], acc[mf][nf][3]);
            if (EPI == EPI_BIAS_RES) {
                float2 e0 = *reinterpret_cast<const float2*>(&res[r0 * N + col]);
                float2 e1 = *reinterpret_cast<const float2*>(&res[r1 * N + col]);
                v0.x += bv[nf].x + e0.x; v0.y += bv[nf].y + e0.y;
                v1.x += bv[nf].x + e1.x; v1.y += bv[nf].y + e1.y;
            } else if (EPI == EPI_GELU_BIAS) {
                v0.x = gelu_exact(v0.x + bv[nf].x);
                v0.y = gelu_exact(v0.y + bv[nf].y);
                v1.x = gelu_exact(v1.x + bv[nf].x);
                v1.y = gelu_exact(v1.y + bv[nf].y);
            } else if (EPI == EPI_BIAS_ACC) {
                float2 e0 = *reinterpret_cast<const float2*>(&C[r0 * N + col]);
                float2 e1 = *reinterpret_cast<const float2*>(&C[r1 * N + col]);
                v0.x += bv[nf].x + e0.x; v0.y += bv[nf].y + e0.y;
                v1.x += bv[nf].x + e1.x; v1.y += bv[nf].y + e1.y;
            }
            *reinterpret_cast<float2*>(&C[r0 * N + col]) = v0;
            *reinterpret_cast<float2*>(&C[r1 * N + col]) = v1;
        }
    }
}

// ---------------------------------------------------------------------------
// Shifted-window attention (fp32), one block per (window, head, batch)
// ---------------------------------------------------------------------------
__global__ __launch_bounds__(256)
void attn_kernel(const float* __restrict__ qkv,
                 const float* __restrict__ pos,
                 float* __restrict__ out)
{
    int w   = blockIdx.x;
    int h   = blockIdx.y;
    int b   = blockIdx.z;
    int tid = threadIdx.x;

    __shared__ float q[WS][HDIM], k[WS][HDIM], v[WS][HDIM];
    __shared__ float dots[WS][WS + 1];

    #pragma unroll
    for (int it = 0; it < 2; it++) {
        int slot = tid + it * 256;
        int row  = slot >> 3, c4 = slot & 7;
        long t = (long)b * NPB + ((w * WS + WS / 2 + row) & (NPB - 1));
        const float* base = qkv + t * 768 + h * HDIM + c4 * 4;
        *reinterpret_cast<float4*>(&q[row][c4 * 4]) =
            *reinterpret_cast<const float4*>(base);
        *reinterpret_cast<float4*>(&k[row][c4 * 4]) =
            *reinterpret_cast<const float4*>(base + 256);
        *reinterpret_cast<float4*>(&v[row][c4 * 4]) =
            *reinterpret_cast<const float4*>(base + 512);
    }
    __syncthreads();

    const float scale = 0.17677669529663687f;
    #pragma unroll
    for (int it = 0; it < 16; it++) {
        int e = tid + it * 256;
        int i = e >> 6, j = e & 63;
        float s = 0.f;
        #pragma unroll
        for (int d = 0; d < HDIM; d++) s = fmaf(q[i][d], k[j][d], s);
        dots[i][j] = s * scale + pos[i * WS + j];
    }
    __syncthreads();

    if (tid < WS) {
        float m = -INFINITY;
        #pragma unroll 8
        for (int j = 0; j < WS; j++) m = fmaxf(m, dots[tid][j]);
        float sum = 0.f;
        #pragma unroll 8
        for (int j = 0; j < WS; j++) {
            float e = expf(dots[tid][j] - m);
            dots[tid][j] = e;
            sum += e;
        }
        float inv = 1.f / sum;
        #pragma unroll 8
        for (int j = 0; j < WS; j++) dots[tid][j] *= inv;
    }
    __syncthreads();

    #pragma unroll
    for (int it = 0; it < 8; it++) {
        int e = tid + it * 256;
        int i = e >> 5, d = e & 31;
        float s = 0.f;
        #pragma unroll
        for (int j = 0; j < WS; j++) s = fmaf(dots[i][j], v[j][d], s);
        long t = (long)b * NPB + ((w * WS + WS / 2 + i) & (NPB - 1));
        out[t * DIMC + h * HDIM + d] = s;
    }
}

// ---------------------------------------------------------------------------
// launch
// ---------------------------------------------------------------------------
extern "C" void kernel_launch(void* const* d_in, const int* in_sizes, int n_in,
                              void* d_out, int out_size)
{
    const float* x      = (const float*)d_in[0];
    const float* w_qkv  = (const float*)d_in[1];
    const float* w_out  = (const float*)d_in[2];
    const float* b_out  = (const float*)d_in[3];
    const float* pos    = (const float*)d_in[4];
    const float* ln1_g  = (const float*)d_in[5];
    const float* ln1_b  = (const float*)d_in[6];
    const float* w1     = (const float*)d_in[7];
    const float* b1     = (const float*)d_in[8];
    const float* w2     = (const float*)d_in[9];
    const float* b2     = (const float*)d_in[10];
    const float* ln2_g  = (const float*)d_in[11];
    const float* ln2_b  = (const float*)d_in[12];
    float* out = (float*)d_out;

    int tokens = in_sizes[0] / DIMC;   // 131072

    float *p_ln, *p_qkv, *p_attn, *p_h, *p_wqkvT, *p_woutT, *p_w1T, *p_w2T;
    cudaGetSymbolAddress((void**)&p_ln,    g_ln);
    cudaGetSymbolAddress((void**)&p_qkv,   g_qkv);
    cudaGetSymbolAddress((void**)&p_attn,  g_attn);
    cudaGetSymbolAddress((void**)&p_h,     g_h);
    cudaGetSymbolAddress((void**)&p_wqkvT, g_wqkvT);
    cudaGetSymbolAddress((void**)&p_woutT, g_woutT);
    cudaGetSymbolAddress((void**)&p_w1T,   g_w1T);
    cudaGetSymbolAddress((void**)&p_w2T,   g_w2T);

    cudaFuncSetAttribute(tc_gemm<EPI_NONE>,
        cudaFuncAttributeMaxDynamicSharedMemorySize, GEMM_SMEM_BYTES);
    cudaFuncSetAttribute(tc_gemm<EPI_BIAS_RES>,
        cudaFuncAttributeMaxDynamicSharedMemorySize, GEMM_SMEM_BYTES);
    cudaFuncSetAttribute(tc_gemm<EPI_GELU_BIAS>,
        cudaFuncAttributeMaxDynamicSharedMemorySize, GEMM_SMEM_BYTES);
    cudaFuncSetAttribute(tc_gemm<EPI_BIAS_ACC>,
        cudaFuncAttributeMaxDynamicSharedMemorySize, GEMM_SMEM_BYTES);

    // transposed weights [N,K]
    {
        dim3 blk(32, 8);
        transpose_kernel<<<dim3(768 / 32,  DIMC / 32), blk>>>(w_qkv, p_wqkvT, DIMC, 768);
        transpose_kernel<<<dim3(DIMC / 32, DIMC / 32), blk>>>(w_out, p_woutT, DIMC, DIMC);
        transpose_kernel<<<dim3(MLPD / 32, DIMC / 32), blk>>>(w1,    p_w1T,   DIMC, MLPD);
        transpose_kernel<<<dim3(DIMC / 32, MLPD / 32), blk>>>(w2,    p_w2T,   MLPD, DIMC);
    }

    // 1) LN1
    ln_kernel<<<tokens, 256>>>(x, ln1_g, ln1_b, p_ln);

    // 2) QKV = LN1(x) @ w_qkv
    {
        dim3 grid(768 / BN, tokens / BM);
        tc_gemm<EPI_NONE><<<grid, 256, GEMM_SMEM_BYTES>>>(
            p_ln, p_wqkvT, p_qkv, nullptr, nullptr, tokens, 768, DIMC);
    }

    // 3) windowed attention
    {
        dim3 grid(NPB / WS, HEADS, tokens / NPB);
        attn_kernel<<<grid, 256>>>(p_qkv, pos, p_attn);
    }

    // 4) x2 = x + attn @ w_out + b_out -> d_out
    {
        dim3 grid(DIMC / BN, tokens / BM);
        tc_gemm<EPI_BIAS_RES><<<grid, 256, GEMM_SMEM_BYTES>>>(
            p_attn, p_woutT, out, b_out, x, tokens, DIMC, DIMC);
    }

    // 5) LN2
    ln_kernel<<<tokens, 256>>>(out, ln2_g, ln2_b, p_ln);

    // 6) h = gelu(LN2 @ w1 + b1)
    {
        dim3 grid(MLPD / BN, tokens / BM);
        tc_gemm<EPI_GELU_BIAS><<<grid, 256, GEMM_SMEM_BYTES>>>(
            p_ln, p_w1T, p_h, b1, nullptr, tokens, MLPD, DIMC);
    }

    // 7) out += h @ w2 + b2
    {
        dim3 grid(DIMC / BN, tokens / BM);
        tc_gemm<EPI_BIAS_ACC><<<grid, 256, GEMM_SMEM_BYTES>>>(
            p_h, p_w2T, out, b2, nullptr, tokens, DIMC, MLPD);
    }
}

// round 4
// speedup vs baseline: 2.3904x; 1.2538x over previous
#include <cuda_runtime.h>
#include <math.h>
#include <stdint.h>

// ---------------------------------------------------------------------------
// PointSwinBlock on GB300 (sm_103): tf32 mma.sync GEMMs, cp.async 3-stage
// pipeline, operands pre-rounded to tf32 in producer kernels.
// B=2, N=65536, DIM=256, HEADS=8, HEAD_DIM=32, WS=64, MLP=1024
// ---------------------------------------------------------------------------

#define DIMC   256
#define NTOK   131072
#define NPB    65536
#define HEADS  8
#define HDIM   32
#define WS     64
#define MLPD   1024

// scratch (allocation-free: __device__ globals)
__device__ float g_ln  [(size_t)NTOK * DIMC];
__device__ float g_qkv [(size_t)NTOK * 768];
__device__ float g_attn[(size_t)NTOK * DIMC];
__device__ float g_h   [(size_t)NTOK * MLPD];
// transposed weights [N,K] (tf32-rounded)
__device__ float g_wqkvT[768 * DIMC];
__device__ float g_woutT[DIMC * DIMC];
__device__ float g_w1T  [MLPD * DIMC];
__device__ float g_w2T  [DIMC * MLPD];

__device__ __forceinline__ uint32_t f2tf32(float f) {
    uint32_t u;
    asm("cvt.rna.tf32.f32 %0, %1;" : "=r"(u) : "f"(f));
    return u;
}
__device__ __forceinline__ float tf32r(float f) {
    return __uint_as_float(f2tf32(f));
}

__device__ __forceinline__ uint32_t smem_u32(const void* p) {
    uint32_t a;
    asm("{ .reg .u64 t; cvta.to.shared.u64 t, %1; cvt.u32.u64 %0, t; }"
        : "=r"(a) : "l"(p));
    return a;
}

__device__ __forceinline__ void cpa16(uint32_t dst, const float* src) {
    asm volatile("cp.async.cg.shared.global [%0], [%1], 16;"
                 :: "r"(dst), "l"(src) : "memory");
}
#define CPA_COMMIT() asm volatile("cp.async.commit_group;" ::: "memory")

__device__ __forceinline__ void mma_tf32(float* d, const uint32_t* a,
                                         const uint32_t* b) {
    asm volatile(
        "mma.sync.aligned.m16n8k8.row.col.f32.tf32.tf32.f32 "
        "{%0,%1,%2,%3}, {%4,%5,%6,%7}, {%8,%9}, {%0,%1,%2,%3};"
        : "+f"(d[0]), "+f"(d[1]), "+f"(d[2]), "+f"(d[3])
        : "r"(a[0]), "r"(a[1]), "r"(a[2]), "r"(a[3]),
          "r"(b[0]), "r"(b[1]));
}

__device__ __forceinline__ float gelu_exact(float v)
{
    return 0.5f * v * (1.f + erff(v * 0.7071067811865476f));
}

// ---------------------------------------------------------------------------
// LayerNorm: one block per row, 256 threads. Output tf32-rounded (GEMM operand).
// ---------------------------------------------------------------------------
__global__ void ln_kernel(const float* __restrict__ x,
                          const float* __restrict__ g,
                          const float* __restrict__ b,
                          float* __restrict__ y)
{
    long row = blockIdx.x;
    int  t   = threadIdx.x;
    float v  = x[row * DIMC + t];
    float s  = v, s2 = v * v;
    #pragma unroll
    for (int o = 16; o; o >>= 1) {
        s  += __shfl_xor_sync(0xffffffffu, s,  o);
        s2 += __shfl_xor_sync(0xffffffffu, s2, o);
    }
    __shared__ float ss[8], ss2[8];
    int w = t >> 5, l = t & 31;
    if (l == 0) { ss[w] = s; ss2[w] = s2; }
    __syncthreads();
    if (t < 32) {
        float a  = (l < 8) ? ss[l]  : 0.f;
        float a2 = (l < 8) ? ss2[l] : 0.f;
        #pragma unroll
        for (int o = 4; o; o >>= 1) {
            a  += __shfl_xor_sync(0xffffffffu, a,  o);
            a2 += __shfl_xor_sync(0xffffffffu, a2, o);
        }
        if (l == 0) { ss[0] = a; ss2[0] = a2; }
    }
    __syncthreads();
    float mu  = ss[0]  * (1.f / DIMC);
    float var = ss2[0] * (1.f / DIMC) - mu * mu;
    float inv = rsqrtf(var + 1e-5f);
    y[row * DIMC + t] = tf32r((v - mu) * inv * g[t] + b[t]);
}

// ---------------------------------------------------------------------------
// Weight transpose: in[R,C] -> out[C,R], tf32-rounded
// ---------------------------------------------------------------------------
__global__ void transpose_kernel(const float* __restrict__ in,
                                 float* __restrict__ out, int R, int C)
{
    __shared__ float t[32][33];
    int bx = blockIdx.x * 32, by = blockIdx.y * 32;
    #pragma unroll
    for (int i = threadIdx.y; i < 32; i += 8)
        t[i][threadIdx.x] = in[(long)(by + i) * C + bx + threadIdx.x];
    __syncthreads();
    #pragma unroll
    for (int i = threadIdx.y; i < 32; i += 8)
        out[(long)(bx + i) * R + by + threadIdx.x] = tf32r(t[threadIdx.x][i]);
}

// ---------------------------------------------------------------------------
// tf32 mma.sync GEMM: C[M,N] = A[M,K] @ Bt[N,K]^T (+ epilogue).
// 128x128 block tile, BK=32, 8 warps (2m x 4n), warp tile 64x32.
// 3-stage cp.async pipeline, fp32 operands already tf32-valued.
// smem/stage: A 128x32f (16KB) + B 128x32f (16KB). 96KB total, 2 CTAs/SM.
// ---------------------------------------------------------------------------
#define EPI_NONE      0
#define EPI_BIAS_RES  1
#define EPI_GELU_BIAS 2
#define EPI_BIAS_ACC  3

#define BM 128
#define BN 128
#define BK 32
#define STAGES 3
#define STG_F  8192                 // floats per stage (A 4096 + B 4096)
#define GEMM_SMEM_BYTES (STAGES * STG_F * 4)   // 98304

// smem float index: stage base + row*32 + ((grp ^ (row&7))<<2) + e
__device__ __forceinline__ int sw_idx(int row, int grp, int e) {
    return row * 32 + (((grp) ^ (row & 7)) << 2) + e;
}

template <int EPI>
__global__ __launch_bounds__(256, 2)
void tc_gemm(const float* __restrict__ A, const float* __restrict__ Bt,
             float* __restrict__ C,
             const float* __restrict__ bias,
             const float* __restrict__ res,
             int M, int N, int K)
{
    extern __shared__ float smf[];
    uint32_t sbase = smem_u32(smf);

    int  tid    = threadIdx.x;
    int  lane   = tid & 31;
    int  wid    = tid >> 5;
    int  warp_m = wid >> 2;          // 0..1
    int  warp_n = wid & 3;           // 0..3
    long m0     = (long)blockIdx.y * BM;
    int  n0     = blockIdx.x * BN;
    int  nc     = K / BK;

    int l_row = tid >> 3;            // 0..31 (+32 per it)
    int l_c4  = tid & 7;             // 16B group
    int l_grp = (l_c4 ^ (l_row & 7));
    uint32_t l_off = (uint32_t)(l_row * 32 + (l_grp << 2)) * 4;

    auto ldgsts = [&](int kc, int st) {
        uint32_t sb = sbase + (uint32_t)(st * STG_F) * 4 + l_off;
        const float* Ap = A  + (m0 + l_row) * K + kc * BK + l_c4 * 4;
        const float* Bp = Bt + ((long)n0 + l_row) * K + kc * BK + l_c4 * 4;
        #pragma unroll
        for (int it = 0; it < 4; it++) {
            uint32_t so = sb + (uint32_t)(it * 32 * 32) * 4;
            cpa16(so,             Ap + (long)(it * 32) * K);
            cpa16(so + 4096 * 4,  Bp + (long)(it * 32) * K);
        }
        CPA_COMMIT();
    };

    float acc[4][4][4];
    #pragma unroll
    for (int i = 0; i < 4; i++)
        #pragma unroll
        for (int j = 0; j < 4; j++)
            #pragma unroll
            for (int e = 0; e < 4; e++) acc[i][j][e] = 0.f;

    ldgsts(0, 0);
    ldgsts(1, 1);

    int g = lane >> 2;       // groupID (row/col within fragment)
    int q = lane & 3;
    int gx = g & 7;          // swizzle xor for all fragment rows

    for (int c = 0; c < nc; c++) {
        if (c + 2 < nc) ldgsts(c + 2, (c + 2) % STAGES);

        if (c + 2 < nc)      asm volatile("cp.async.wait_group 2;" ::: "memory");
        else if (c + 1 < nc) asm volatile("cp.async.wait_group 1;" ::: "memory");
        else                 asm volatile("cp.async.wait_group 0;" ::: "memory");
        __syncthreads();

        const uint32_t* smA = reinterpret_cast<const uint32_t*>(
            smf + (c % STAGES) * STG_F);
        const uint32_t* smB = smA + 4096;

        #pragma unroll
        for (int ks = 0; ks < 4; ks++) {
            int glo = (2 * ks)     ^ gx;
            int ghi = (2 * ks + 1) ^ gx;
            uint32_t af[4][4];
            #pragma unroll
            for (int mf = 0; mf < 4; mf++) {
                int r0 = warp_m * 64 + mf * 16 + g;
                int r1 = r0 + 8;
                af[mf][0] = smA[r0 * 32 + (glo << 2) + q];
                af[mf][1] = smA[r1 * 32 + (glo << 2) + q];
                af[mf][2] = smA[r0 * 32 + (ghi << 2) + q];
                af[mf][3] = smA[r1 * 32 + (ghi << 2) + q];
            }
            uint32_t bf[4][2];
            #pragma unroll
            for (int nf = 0; nf < 4; nf++) {
                int col = warp_n * 32 + nf * 8 + g;
                bf[nf][0] = smB[col * 32 + (glo << 2) + q];
                bf[nf][1] = smB[col * 32 + (ghi << 2) + q];
            }
            #pragma unroll
            for (int mf = 0; mf < 4; mf++)
                #pragma unroll
                for (int nf = 0; nf < 4; nf++)
                    mma_tf32(acc[mf][nf], af[mf], bf[nf]);
        }
        __syncthreads();
    }

    // epilogue: frag rows g, g+8; cols 2q, 2q+1
    float2 bv[4];
    if (EPI != EPI_NONE) {
        #pragma unroll
        for (int nf = 0; nf < 4; nf++) {
            int col = n0 + warp_n * 32 + nf * 8 + q * 2;
            bv[nf] = *reinterpret_cast<const float2*>(&bias[col]);
        }
    }

    #pragma unroll
    for (int mf = 0; mf < 4; mf++) {
        long r0 = m0 + warp_m * 64 + mf * 16 + g;
        long r1 = r0 + 8;
        #pragma unroll
        for (int nf = 0; nf < 4; nf++) {
            int col = n0 + warp_n * 32 + nf * 8 + q * 2;
            float2 v0 = make_float2(acc[mf][nf][0], acc[mf][nf][1]);
            float2 v1 = make_float2(acc[mf][nf][2], acc[mf][nf][3]);
            if (EPI == EPI_BIAS_RES) {
                float2 e0 = *reinterpret_cast<const float2*>(&res[r0 * N + col]);
                float2 e1 = *reinterpret_cast<const float2*>(&res[r1 * N + col]);
                v0.x += bv[nf].x + e0.x; v0.y += bv[nf].y + e0.y;
                v1.x += bv[nf].x + e1.x; v1.y += bv[nf].y + e1.y;
            } else if (EPI == EPI_GELU_BIAS) {
                // output is a GEMM operand -> tf32-round it here
                v0.x = tf32r(gelu_exact(v0.x + bv[nf].x));
                v0.y = tf32r(gelu_exact(v0.y + bv[nf].y));
                v1.x = tf32r(gelu_exact(v1.x + bv[nf].x));
                v1.y = tf32r(gelu_exact(v1.y + bv[nf].y));
            } else if (EPI == EPI_BIAS_ACC) {
                float2 e0 = *reinterpret_cast<const float2*>(&C[r0 * N + col]);
                float2 e1 = *reinterpret_cast<const float2*>(&C[r1 * N + col]);
                v0.x += bv[nf].x + e0.x; v0.y += bv[nf].y + e0.y;
                v1.x += bv[nf].x + e1.x; v1.y += bv[nf].y + e1.y;
            }
            *reinterpret_cast<float2*>(&C[r0 * N + col]) = v0;
            *reinterpret_cast<float2*>(&C[r1 * N + col]) = v1;
        }
    }
}

// ---------------------------------------------------------------------------
// Shifted-window attention (fp32), one block per (window, head, batch).
// Output tf32-rounded (GEMM operand).
// ---------------------------------------------------------------------------
__global__ __launch_bounds__(256)
void attn_kernel(const float* __restrict__ qkv,
                 const float* __restrict__ pos,
                 float* __restrict__ out)
{
    int w   = blockIdx.x;
    int h   = blockIdx.y;
    int b   = blockIdx.z;
    int tid = threadIdx.x;

    __shared__ float q[WS][HDIM], k[WS][HDIM], v[WS][HDIM];
    __shared__ float dots[WS][WS + 1];

    #pragma unroll
    for (int it = 0; it < 2; it++) {
        int slot = tid + it * 256;
        int row  = slot >> 3, c4 = slot & 7;
        long t = (long)b * NPB + ((w * WS + WS / 2 + row) & (NPB - 1));
        const float* base = qkv + t * 768 + h * HDIM + c4 * 4;
        *reinterpret_cast<float4*>(&q[row][c4 * 4]) =
            *reinterpret_cast<const float4*>(base);
        *reinterpret_cast<float4*>(&k[row][c4 * 4]) =
            *reinterpret_cast<const float4*>(base + 256);
        *reinterpret_cast<float4*>(&v[row][c4 * 4]) =
            *reinterpret_cast<const float4*>(base + 512);
    }
    __syncthreads();

    const float scale = 0.17677669529663687f;
    #pragma unroll
    for (int it = 0; it < 16; it++) {
        int e = tid + it * 256;
        int i = e >> 6, j = e & 63;
        float s = 0.f;
        #pragma unroll
        for (int d = 0; d < HDIM; d++) s = fmaf(q[i][d], k[j][d], s);
        dots[i][j] = s * scale + pos[i * WS + j];
    }
    __syncthreads();

    if (tid < WS) {
        float m = -INFINITY;
        #pragma unroll 8
        for (int j = 0; j < WS; j++) m = fmaxf(m, dots[tid][j]);
        float sum = 0.f;
        #pragma unroll 8
        for (int j = 0; j < WS; j++) {
            float e = expf(dots[tid][j] - m);
            dots[tid][j] = e;
            sum += e;
        }
        float inv = 1.f / sum;
        #pragma unroll 8
        for (int j = 0; j < WS; j++) dots[tid][j] *= inv;
    }
    __syncthreads();

    #pragma unroll
    for (int it = 0; it < 8; it++) {
        int e = tid + it * 256;
        int i = e >> 5, d = e & 31;
        float s = 0.f;
        #pragma unroll
        for (int j = 0; j < WS; j++) s = fmaf(dots[i][j], v[j][d], s);
        long t = (long)b * NPB + ((w * WS + WS / 2 + i) & (NPB - 1));
        out[t * DIMC + h * HDIM + d] = tf32r(s);
    }
}

// ---------------------------------------------------------------------------
// launch
// ---------------------------------------------------------------------------
extern "C" void kernel_launch(void* const* d_in, const int* in_sizes, int n_in,
                              void* d_out, int out_size)
{
    const float* x      = (const float*)d_in[0];
    const float* w_qkv  = (const float*)d_in[1];
    const float* w_out  = (const float*)d_in[2];
    const float* b_out  = (const float*)d_in[3];
    const float* pos    = (const float*)d_in[4];
    const float* ln1_g  = (const float*)d_in[5];
    const float* ln1_b  = (const float*)d_in[6];
    const float* w1     = (const float*)d_in[7];
    const float* b1     = (const float*)d_in[8];
    const float* w2     = (const float*)d_in[9];
    const float* b2     = (const float*)d_in[10];
    const float* ln2_g  = (const float*)d_in[11];
    const float* ln2_b  = (const float*)d_in[12];
    float* out = (float*)d_out;

    int tokens = in_sizes[0] / DIMC;   // 131072

    float *p_ln, *p_qkv, *p_attn, *p_h, *p_wqkvT, *p_woutT, *p_w1T, *p_w2T;
    cudaGetSymbolAddress((void**)&p_ln,    g_ln);
    cudaGetSymbolAddress((void**)&p_qkv,   g_qkv);
    cudaGetSymbolAddress((void**)&p_attn,  g_attn);
    cudaGetSymbolAddress((void**)&p_h,     g_h);
    cudaGetSymbolAddress((void**)&p_wqkvT, g_wqkvT);
    cudaGetSymbolAddress((void**)&p_woutT, g_woutT);
    cudaGetSymbolAddress((void**)&p_w1T,   g_w1T);
    cudaGetSymbolAddress((void**)&p_w2T,   g_w2T);

    cudaFuncSetAttribute(tc_gemm<EPI_NONE>,
        cudaFuncAttributeMaxDynamicSharedMemorySize, GEMM_SMEM_BYTES);
    cudaFuncSetAttribute(tc_gemm<EPI_BIAS_RES>,
        cudaFuncAttributeMaxDynamicSharedMemorySize, GEMM_SMEM_BYTES);
    cudaFuncSetAttribute(tc_gemm<EPI_GELU_BIAS>,
        cudaFuncAttributeMaxDynamicSharedMemorySize, GEMM_SMEM_BYTES);
    cudaFuncSetAttribute(tc_gemm<EPI_BIAS_ACC>,
        cudaFuncAttributeMaxDynamicSharedMemorySize, GEMM_SMEM_BYTES);

    // transposed + tf32-rounded weights [N,K]
    {
        dim3 blk(32, 8);
        transpose_kernel<<<dim3(768 / 32,  DIMC / 32), blk>>>(w_qkv, p_wqkvT, DIMC, 768);
        transpose_kernel<<<dim3(DIMC / 32, DIMC / 32), blk>>>(w_out, p_woutT, DIMC, DIMC);
        transpose_kernel<<<dim3(MLPD / 32, DIMC / 32), blk>>>(w1,    p_w1T,   DIMC, MLPD);
        transpose_kernel<<<dim3(DIMC / 32, MLPD / 32), blk>>>(w2,    p_w2T,   MLPD, DIMC);
    }

    // 1) LN1
    ln_kernel<<<tokens, 256>>>(x, ln1_g, ln1_b, p_ln);

    // 2) QKV = LN1(x) @ w_qkv
    {
        dim3 grid(768 / BN, tokens / BM);
        tc_gemm<EPI_NONE><<<grid, 256, GEMM_SMEM_BYTES>>>(
            p_ln, p_wqkvT, p_qkv, nullptr, nullptr, tokens, 768, DIMC);
    }

    // 3) windowed attention
    {
        dim3 grid(NPB / WS, HEADS, tokens / NPB);
        attn_kernel<<<grid, 256>>>(p_qkv, pos, p_attn);
    }

    // 4) x2 = x + attn @ w_out + b_out -> d_out
    {
        dim3 grid(DIMC / BN, tokens / BM);
        tc_gemm<EPI_BIAS_RES><<<grid, 256, GEMM_SMEM_BYTES>>>(
            p_attn, p_woutT, out, b_out, x, tokens, DIMC, DIMC);
    }

    // 5) LN2
    ln_kernel<<<tokens, 256>>>(out, ln2_g, ln2_b, p_ln);

    // 6) h = gelu(LN2 @ w1 + b1)  (tf32-rounded)
    {
        dim3 grid(MLPD / BN, tokens / BM);
        tc_gemm<EPI_GELU_BIAS><<<grid, 256, GEMM_SMEM_BYTES>>>(
            p_ln, p_w1T, p_h, b1, nullptr, tokens, MLPD, DIMC);
    }

    // 7) out += h @ w2 + b2
    {
        dim3 grid(DIMC / BN, tokens / BM);
        tc_gemm<EPI_BIAS_ACC><<<grid, 256, GEMM_SMEM_BYTES>>>(
            p_h, p_w2T, out, b2, nullptr, tokens, DIMC, MLPD);
    }
}

// round 5
// speedup vs baseline: 2.4064x; 1.0067x over previous
#include <cuda_runtime.h>
#include <math.h>
#include <stdint.h>

// ---------------------------------------------------------------------------
// PointSwinBlock on GB300 (sm_103): tf32 mma.sync GEMMs, BM128xBN256 tiles,
// 4-stage cp.async pipeline, operands pre-rounded to tf32 by producers.
// B=2, N=65536, DIM=256, HEADS=8, HEAD_DIM=32, WS=64, MLP=1024
// ---------------------------------------------------------------------------

#define DIMC   256
#define NTOK   131072
#define NPB    65536
#define HEADS  8
#define HDIM   32
#define WS     64
#define MLPD   1024

// scratch (allocation-free: __device__ globals)
__device__ float g_ln  [(size_t)NTOK * DIMC];
__device__ float g_qkv [(size_t)NTOK * 768];
__device__ float g_attn[(size_t)NTOK * DIMC];
__device__ float g_h   [(size_t)NTOK * MLPD];
// transposed weights [N,K] (tf32-rounded)
__device__ float g_wqkvT[768 * DIMC];
__device__ float g_woutT[DIMC * DIMC];
__device__ float g_w1T  [MLPD * DIMC];
__device__ float g_w2T  [DIMC * MLPD];

__device__ __forceinline__ uint32_t f2tf32(float f) {
    uint32_t u;
    asm("cvt.rna.tf32.f32 %0, %1;" : "=r"(u) : "f"(f));
    return u;
}
__device__ __forceinline__ float tf32r(float f) {
    return __uint_as_float(f2tf32(f));
}

__device__ __forceinline__ uint32_t smem_u32(const void* p) {
    uint32_t a;
    asm("{ .reg .u64 t; cvta.to.shared.u64 t, %1; cvt.u32.u64 %0, t; }"
        : "=r"(a) : "l"(p));
    return a;
}

__device__ __forceinline__ void cpa16(uint32_t dst, const float* src) {
    asm volatile("cp.async.cg.shared.global [%0], [%1], 16;"
                 :: "r"(dst), "l"(src) : "memory");
}
#define CPA_COMMIT() asm volatile("cp.async.commit_group;" ::: "memory")

__device__ __forceinline__ void mma_tf32(float* d, const uint32_t* a,
                                         const uint32_t* b) {
    asm volatile(
        "mma.sync.aligned.m16n8k8.row.col.f32.tf32.tf32.f32 "
        "{%0,%1,%2,%3}, {%4,%5,%6,%7}, {%8,%9}, {%0,%1,%2,%3};"
        : "+f"(d[0]), "+f"(d[1]), "+f"(d[2]), "+f"(d[3])
        : "r"(a[0]), "r"(a[1]), "r"(a[2]), "r"(a[3]),
          "r"(b[0]), "r"(b[1]));
}

__device__ __forceinline__ float gelu_exact(float v)
{
    return 0.5f * v * (1.f + erff(v * 0.7071067811865476f));
}

// ---------------------------------------------------------------------------
// LayerNorm: one block per row, 256 threads. Output tf32-rounded.
// ---------------------------------------------------------------------------
__global__ void ln_kernel(const float* __restrict__ x,
                          const float* __restrict__ g,
                          const float* __restrict__ b,
                          float* __restrict__ y)
{
    long row = blockIdx.x;
    int  t   = threadIdx.x;
    float v  = x[row * DIMC + t];
    float s  = v, s2 = v * v;
    #pragma unroll
    for (int o = 16; o; o >>= 1) {
        s  += __shfl_xor_sync(0xffffffffu, s,  o);
        s2 += __shfl_xor_sync(0xffffffffu, s2, o);
    }
    __shared__ float ss[8], ss2[8];
    int w = t >> 5, l = t & 31;
    if (l == 0) { ss[w] = s; ss2[w] = s2; }
    __syncthreads();
    if (t < 32) {
        float a  = (l < 8) ? ss[l]  : 0.f;
        float a2 = (l < 8) ? ss2[l] : 0.f;
        #pragma unroll
        for (int o = 4; o; o >>= 1) {
            a  += __shfl_xor_sync(0xffffffffu, a,  o);
            a2 += __shfl_xor_sync(0xffffffffu, a2, o);
        }
        if (l == 0) { ss[0] = a; ss2[0] = a2; }
    }
    __syncthreads();
    float mu  = ss[0]  * (1.f / DIMC);
    float var = ss2[0] * (1.f / DIMC) - mu * mu;
    float inv = rsqrtf(var + 1e-5f);
    y[row * DIMC + t] = tf32r((v - mu) * inv * g[t] + b[t]);
}

// ---------------------------------------------------------------------------
// Weight transpose: in[R,C] -> out[C,R], tf32-rounded
// ---------------------------------------------------------------------------
__global__ void transpose_kernel(const float* __restrict__ in,
                                 float* __restrict__ out, int R, int C)
{
    __shared__ float t[32][33];
    int bx = blockIdx.x * 32, by = blockIdx.y * 32;
    #pragma unroll
    for (int i = threadIdx.y; i < 32; i += 8)
        t[i][threadIdx.x] = in[(long)(by + i) * C + bx + threadIdx.x];
    __syncthreads();
    #pragma unroll
    for (int i = threadIdx.y; i < 32; i += 8)
        out[(long)(bx + i) * R + by + threadIdx.x] = tf32r(t[threadIdx.x][i]);
}

// ---------------------------------------------------------------------------
// tf32 mma.sync GEMM: C[M,N] = A[M,K] @ Bt[N,K]^T (+ epilogue).
// 128x256 block tile, BK=32, 8 warps (2m x 4n), warp tile 64x64.
// 4-stage cp.async pipeline (prefetch depth 3), 192KB smem, 1 CTA/SM.
// ---------------------------------------------------------------------------
#define EPI_NONE      0
#define EPI_BIAS_RES  1
#define EPI_GELU_BIAS 2
#define EPI_BIAS_ACC  3

#define BM 128
#define BN 256
#define BK 32
#define STAGES 4
#define A_F    4096                  // A floats per stage (128*32)
#define B_F    8192                  // B floats per stage (256*32)
#define STG_F  (A_F + B_F)           // 12288
#define GEMM_SMEM_BYTES (STAGES * STG_F * 4)   // 196608

template <int EPI>
__global__ __launch_bounds__(256, 1)
void tc_gemm(const float* __restrict__ A, const float* __restrict__ Bt,
             float* __restrict__ C,
             const float* __restrict__ bias,
             const float* __restrict__ res,
             int M, int N, int K)
{
    extern __shared__ float smf[];
    uint32_t sbase = smem_u32(smf);

    int  tid    = threadIdx.x;
    int  lane   = tid & 31;
    int  wid    = tid >> 5;
    int  warp_m = wid >> 2;          // 0..1 (64 rows)
    int  warp_n = wid & 3;           // 0..3 (64 cols)
    long m0     = (long)blockIdx.y * BM;
    int  n0     = blockIdx.x * BN;
    int  nc     = K / BK;

    int l_row = tid >> 3;            // 0..31 (+32 per it)
    int l_c4  = tid & 7;             // 16B group within 32-float row
    uint32_t l_off = (uint32_t)(l_row * 32 + ((l_c4 ^ (l_row & 7)) << 2)) * 4;

    auto ldgsts = [&](int kc, int st) {
        uint32_t sb = sbase + (uint32_t)(st * STG_F) * 4 + l_off;
        const float* Ap = A  + (m0 + l_row) * K + kc * BK + l_c4 * 4;
        #pragma unroll
        for (int it = 0; it < 4; it++)
            cpa16(sb + (uint32_t)(it * 32 * 32) * 4, Ap + (long)(it * 32) * K);
        const float* Bp = Bt + ((long)n0 + l_row) * K + kc * BK + l_c4 * 4;
        #pragma unroll
        for (int it = 0; it < 8; it++)
            cpa16(sb + (uint32_t)(A_F + it * 32 * 32) * 4,
                  Bp + (long)(it * 32) * K);
        CPA_COMMIT();
    };

    float acc[4][8][4];
    #pragma unroll
    for (int i = 0; i < 4; i++)
        #pragma unroll
        for (int j = 0; j < 8; j++)
            #pragma unroll
            for (int e = 0; e < 4; e++) acc[i][j][e] = 0.f;

    ldgsts(0, 0);
    if (nc > 1) ldgsts(1, 1);
    if (nc > 2) ldgsts(2, 2);

    int g  = lane >> 2;      // groupID
    int q  = lane & 3;
    int gx = g & 7;

    for (int c = 0; c < nc; c++) {
        if (c + 3 < nc) ldgsts(c + 3, (c + 3) & 3);

        int rem = nc - 1 - c; if (rem > 3) rem = 3;
        if (rem == 3)      asm volatile("cp.async.wait_group 3;" ::: "memory");
        else if (rem == 2) asm volatile("cp.async.wait_group 2;" ::: "memory");
        else if (rem == 1) asm volatile("cp.async.wait_group 1;" ::: "memory");
        else               asm volatile("cp.async.wait_group 0;" ::: "memory");
        __syncthreads();

        const uint32_t* smA = reinterpret_cast<const uint32_t*>(
            smf + (c & 3) * STG_F);
        const uint32_t* smB = smA + A_F;

        #pragma unroll
        for (int ks = 0; ks < 4; ks++) {
            int glo = (2 * ks)     ^ gx;
            int ghi = (2 * ks + 1) ^ gx;
            uint32_t af[4][4];
            #pragma unroll
            for (int mf = 0; mf < 4; mf++) {
                int r0 = warp_m * 64 + mf * 16 + g;
                int r1 = r0 + 8;
                af[mf][0] = smA[r0 * 32 + (glo << 2) + q];
                af[mf][1] = smA[r1 * 32 + (glo << 2) + q];
                af[mf][2] = smA[r0 * 32 + (ghi << 2) + q];
                af[mf][3] = smA[r1 * 32 + (ghi << 2) + q];
            }
            uint32_t bf[8][2];
            #pragma unroll
            for (int nf = 0; nf < 8; nf++) {
                int col = warp_n * 64 + nf * 8 + g;
                bf[nf][0] = smB[col * 32 + (glo << 2) + q];
                bf[nf][1] = smB[col * 32 + (ghi << 2) + q];
            }
            #pragma unroll
            for (int mf = 0; mf < 4; mf++)
                #pragma unroll
                for (int nf = 0; nf < 8; nf++)
                    mma_tf32(acc[mf][nf], af[mf], bf[nf]);
        }
        __syncthreads();
    }

    // epilogue: frag rows g, g+8; cols 2q, 2q+1
    float2 bv[8];
    if (EPI != EPI_NONE) {
        #pragma unroll
        for (int nf = 0; nf < 8; nf++) {
            int col = n0 + warp_n * 64 + nf * 8 + q * 2;
            bv[nf] = *reinterpret_cast<const float2*>(&bias[col]);
        }
    }

    #pragma unroll
    for (int mf = 0; mf < 4; mf++) {
        long r0 = m0 + warp_m * 64 + mf * 16 + g;
        long r1 = r0 + 8;
        #pragma unroll
        for (int nf = 0; nf < 8; nf++) {
            int col = n0 + warp_n * 64 + nf * 8 + q * 2;
            float2 v0 = make_float2(acc[mf][nf][0], acc[mf][nf][1]);
            float2 v1 = make_float2(acc[mf][nf][2], acc[mf][nf][3]);
            if (EPI == EPI_BIAS_RES) {
                float2 e0 = *reinterpret_cast<const float2*>(&res[r0 * N + col]);
                float2 e1 = *reinterpret_cast<const float2*>(&res[r1 * N + col]);
                v0.x += bv[nf].x + e0.x; v0.y += bv[nf].y + e0.y;
                v1.x += bv[nf].x + e1.x; v1.y += bv[nf].y + e1.y;
            } else if (EPI == EPI_GELU_BIAS) {
                v0.x = tf32r(gelu_exact(v0.x + bv[nf].x));
                v0.y = tf32r(gelu_exact(v0.y + bv[nf].y));
                v1.x = tf32r(gelu_exact(v1.x + bv[nf].x));
                v1.y = tf32r(gelu_exact(v1.y + bv[nf].y));
            } else if (EPI == EPI_BIAS_ACC) {
                float2 e0 = *reinterpret_cast<const float2*>(&C[r0 * N + col]);
                float2 e1 = *reinterpret_cast<const float2*>(&C[r1 * N + col]);
                v0.x += bv[nf].x + e0.x; v0.y += bv[nf].y + e0.y;
                v1.x += bv[nf].x + e1.x; v1.y += bv[nf].y + e1.y;
            }
            *reinterpret_cast<float2*>(&C[r0 * N + col]) = v0;
            *reinterpret_cast<float2*>(&C[r1 * N + col]) = v1;
        }
    }
}

// ---------------------------------------------------------------------------
// Shifted-window attention (fp32), one block per (window, head, batch).
// ---------------------------------------------------------------------------
__global__ __launch_bounds__(256)
void attn_kernel(const float* __restrict__ qkv,
                 const float* __restrict__ pos,
                 float* __restrict__ out)
{
    int w   = blockIdx.x;
    int h   = blockIdx.y;
    int b   = blockIdx.z;
    int tid = threadIdx.x;

    __shared__ float q[WS][HDIM], k[WS][HDIM], v[WS][HDIM];
    __shared__ float dots[WS][WS + 1];

    #pragma unroll
    for (int it = 0; it < 2; it++) {
        int slot = tid + it * 256;
        int row  = slot >> 3, c4 = slot & 7;
        long t = (long)b * NPB + ((w * WS + WS / 2 + row) & (NPB - 1));
        const float* base = qkv + t * 768 + h * HDIM + c4 * 4;
        *reinterpret_cast<float4*>(&q[row][c4 * 4]) =
            *reinterpret_cast<const float4*>(base);
        *reinterpret_cast<float4*>(&k[row][c4 * 4]) =
            *reinterpret_cast<const float4*>(base + 256);
        *reinterpret_cast<float4*>(&v[row][c4 * 4]) =
            *reinterpret_cast<const float4*>(base + 512);
    }
    __syncthreads();

    const float scale = 0.17677669529663687f;
    #pragma unroll
    for (int it = 0; it < 16; it++) {
        int e = tid + it * 256;
        int i = e >> 6, j = e & 63;
        float s = 0.f;
        #pragma unroll
        for (int d = 0; d < HDIM; d++) s = fmaf(q[i][d], k[j][d], s);
        dots[i][j] = s * scale + pos[i * WS + j];
    }
    __syncthreads();

    if (tid < WS) {
        float m = -INFINITY;
        #pragma unroll 8
        for (int j = 0; j < WS; j++) m = fmaxf(m, dots[tid][j]);
        float sum = 0.f;
        #pragma unroll 8
        for (int j = 0; j < WS; j++) {
            float e = expf(dots[tid][j] - m);
            dots[tid][j] = e;
            sum += e;
        }
        float inv = 1.f / sum;
        #pragma unroll 8
        for (int j = 0; j < WS; j++) dots[tid][j] *= inv;
    }
    __syncthreads();

    #pragma unroll
    for (int it = 0; it < 8; it++) {
        int e = tid + it * 256;
        int i = e >> 5, d = e & 31;
        float s = 0.f;
        #pragma unroll
        for (int j = 0; j < WS; j++) s = fmaf(dots[i][j], v[j][d], s);
        long t = (long)b * NPB + ((w * WS + WS / 2 + i) & (NPB - 1));
        out[t * DIMC + h * HDIM + d] = tf32r(s);
    }
}

// ---------------------------------------------------------------------------
// launch
// ---------------------------------------------------------------------------
extern "C" void kernel_launch(void* const* d_in, const int* in_sizes, int n_in,
                              void* d_out, int out_size)
{
    const float* x      = (const float*)d_in[0];
    const float* w_qkv  = (const float*)d_in[1];
    const float* w_out  = (const float*)d_in[2];
    const float* b_out  = (const float*)d_in[3];
    const float* pos    = (const float*)d_in[4];
    const float* ln1_g  = (const float*)d_in[5];
    const float* ln1_b  = (const float*)d_in[6];
    const float* w1     = (const float*)d_in[7];
    const float* b1     = (const float*)d_in[8];
    const float* w2     = (const float*)d_in[9];
    const float* b2     = (const float*)d_in[10];
    const float* ln2_g  = (const float*)d_in[11];
    const float* ln2_b  = (const float*)d_in[12];
    float* out = (float*)d_out;

    int tokens = in_sizes[0] / DIMC;   // 131072

    float *p_ln, *p_qkv, *p_attn, *p_h, *p_wqkvT, *p_woutT, *p_w1T, *p_w2T;
    cudaGetSymbolAddress((void**)&p_ln,    g_ln);
    cudaGetSymbolAddress((void**)&p_qkv,   g_qkv);
    cudaGetSymbolAddress((void**)&p_attn,  g_attn);
    cudaGetSymbolAddress((void**)&p_h,     g_h);
    cudaGetSymbolAddress((void**)&p_wqkvT, g_wqkvT);
    cudaGetSymbolAddress((void**)&p_woutT, g_woutT);
    cudaGetSymbolAddress((void**)&p_w1T,   g_w1T);
    cudaGetSymbolAddress((void**)&p_w2T,   g_w2T);

    cudaFuncSetAttribute(tc_gemm<EPI_NONE>,
        cudaFuncAttributeMaxDynamicSharedMemorySize, GEMM_SMEM_BYTES);
    cudaFuncSetAttribute(tc_gemm<EPI_BIAS_RES>,
        cudaFuncAttributeMaxDynamicSharedMemorySize, GEMM_SMEM_BYTES);
    cudaFuncSetAttribute(tc_gemm<EPI_GELU_BIAS>,
        cudaFuncAttributeMaxDynamicSharedMemorySize, GEMM_SMEM_BYTES);
    cudaFuncSetAttribute(tc_gemm<EPI_BIAS_ACC>,
        cudaFuncAttributeMaxDynamicSharedMemorySize, GEMM_SMEM_BYTES);

    // transposed + tf32-rounded weights [N,K]
    {
        dim3 blk(32, 8);
        transpose_kernel<<<dim3(768 / 32,  DIMC / 32), blk>>>(w_qkv, p_wqkvT, DIMC, 768);
        transpose_kernel<<<dim3(DIMC / 32, DIMC / 32), blk>>>(w_out, p_woutT, DIMC, DIMC);
        transpose_kernel<<<dim3(MLPD / 32, DIMC / 32), blk>>>(w1,    p_w1T,   DIMC, MLPD);
        transpose_kernel<<<dim3(DIMC / 32, MLPD / 32), blk>>>(w2,    p_w2T,   MLPD, DIMC);
    }

    // 1) LN1
    ln_kernel<<<tokens, 256>>>(x, ln1_g, ln1_b, p_ln);

    // 2) QKV = LN1(x) @ w_qkv
    {
        dim3 grid(768 / BN, tokens / BM);
        tc_gemm<EPI_NONE><<<grid, 256, GEMM_SMEM_BYTES>>>(
            p_ln, p_wqkvT, p_qkv, nullptr, nullptr, tokens, 768, DIMC);
    }

    // 3) windowed attention
    {
        dim3 grid(NPB / WS, HEADS, tokens / NPB);
        attn_kernel<<<grid, 256>>>(p_qkv, pos, p_attn);
    }

    // 4) x2 = x + attn @ w_out + b_out -> d_out
    {
        dim3 grid(DIMC / BN, tokens / BM);
        tc_gemm<EPI_BIAS_RES><<<grid, 256, GEMM_SMEM_BYTES>>>(
            p_attn, p_woutT, out, b_out, x, tokens, DIMC, DIMC);
    }

    // 5) LN2
    ln_kernel<<<tokens, 256>>>(out, ln2_g, ln2_b, p_ln);

    // 6) h = gelu(LN2 @ w1 + b1)  (tf32-rounded)
    {
        dim3 grid(MLPD / BN, tokens / BM);
        tc_gemm<EPI_GELU_BIAS><<<grid, 256, GEMM_SMEM_BYTES>>>(
            p_ln, p_w1T, p_h, b1, nullptr, tokens, MLPD, DIMC);
    }

    // 7) out += h @ w2 + b2
    {
        dim3 grid(DIMC / BN, tokens / BM);
        tc_gemm<EPI_BIAS_ACC><<<grid, 256, GEMM_SMEM_BYTES>>>(
            p_h, p_w2T, out, b2, nullptr, tokens, DIMC, MLPD);
    }
}

// round 6
// speedup vs baseline: 3.3515x; 1.3927x over previous
#include <cuda_runtime.h>
#include <cuda_fp16.h>
#include <math.h>
#include <stdint.h>

// ---------------------------------------------------------------------------
// PointSwinBlock on GB300 (sm_103): fp16 mma.sync.m16n8k16 GEMMs (fp32 accum),
// ldmatrix fragments, 3-stage cp.async, half-precision operand storage.
// B=2, N=65536, DIM=256, HEADS=8, HEAD_DIM=32, WS=64, MLP=1024
// ---------------------------------------------------------------------------

#define DIMC   256
#define NTOK   131072
#define NPB    65536
#define HEADS  8
#define HDIM   32
#define WS     64
#define MLPD   1024

// scratch (allocation-free: __device__ globals), GEMM operands in half
__device__ __half g_ln  [(size_t)NTOK * DIMC];
__device__ __half g_qkv [(size_t)NTOK * 768];
__device__ __half g_attn[(size_t)NTOK * DIMC];
__device__ __half g_h   [(size_t)NTOK * MLPD];
// transposed weights [N,K] in half
__device__ __half g_wqkvT[768 * DIMC];
__device__ __half g_woutT[DIMC * DIMC];
__device__ __half g_w1T  [MLPD * DIMC];
__device__ __half g_w2T  [DIMC * MLPD];

__device__ __forceinline__ uint32_t smem_u32(const void* p) {
    uint32_t a;
    asm("{ .reg .u64 t; cvta.to.shared.u64 t, %1; cvt.u32.u64 %0, t; }"
        : "=r"(a) : "l"(p));
    return a;
}

__device__ __forceinline__ void cpa16(uint32_t dst, const void* src) {
    asm volatile("cp.async.cg.shared.global [%0], [%1], 16;"
                 :: "r"(dst), "l"(src) : "memory");
}
#define CPA_COMMIT() asm volatile("cp.async.commit_group;" ::: "memory")

__device__ __forceinline__ void ldsm4(uint32_t& r0, uint32_t& r1,
                                      uint32_t& r2, uint32_t& r3,
                                      uint32_t addr) {
    asm volatile("ldmatrix.sync.aligned.m8n8.x4.shared.b16 {%0,%1,%2,%3}, [%4];"
                 : "=r"(r0), "=r"(r1), "=r"(r2), "=r"(r3) : "r"(addr));
}

__device__ __forceinline__ void mma_f16(float* d, const uint32_t* a,
                                        const uint32_t* b) {
    asm volatile(
        "mma.sync.aligned.m16n8k16.row.col.f32.f16.f16.f32 "
        "{%0,%1,%2,%3}, {%4,%5,%6,%7}, {%8,%9}, {%0,%1,%2,%3};"
        : "+f"(d[0]), "+f"(d[1]), "+f"(d[2]), "+f"(d[3])
        : "r"(a[0]), "r"(a[1]), "r"(a[2]), "r"(a[3]),
          "r"(b[0]), "r"(b[1]));
}

__device__ __forceinline__ float gelu_exact(float v)
{
    return 0.5f * v * (1.f + erff(v * 0.7071067811865476f));
}

// ---------------------------------------------------------------------------
// LayerNorm: one block per row, 256 threads. fp32 in -> half out.
// ---------------------------------------------------------------------------
__global__ void ln_kernel(const float* __restrict__ x,
                          const float* __restrict__ g,
                          const float* __restrict__ b,
                          __half* __restrict__ y)
{
    long row = blockIdx.x;
    int  t   = threadIdx.x;
    float v  = x[row * DIMC + t];
    float s  = v, s2 = v * v;
    #pragma unroll
    for (int o = 16; o; o >>= 1) {
        s  += __shfl_xor_sync(0xffffffffu, s,  o);
        s2 += __shfl_xor_sync(0xffffffffu, s2, o);
    }
    __shared__ float ss[8], ss2[8];
    int w = t >> 5, l = t & 31;
    if (l == 0) { ss[w] = s; ss2[w] = s2; }
    __syncthreads();
    if (t < 32) {
        float a  = (l < 8) ? ss[l]  : 0.f;
        float a2 = (l < 8) ? ss2[l] : 0.f;
        #pragma unroll
        for (int o = 4; o; o >>= 1) {
            a  += __shfl_xor_sync(0xffffffffu, a,  o);
            a2 += __shfl_xor_sync(0xffffffffu, a2, o);
        }
        if (l == 0) { ss[0] = a; ss2[0] = a2; }
    }
    __syncthreads();
    float mu  = ss[0]  * (1.f / DIMC);
    float var = ss2[0] * (1.f / DIMC) - mu * mu;
    float inv = rsqrtf(var + 1e-5f);
    y[row * DIMC + t] = __float2half((v - mu) * inv * g[t] + b[t]);
}

// ---------------------------------------------------------------------------
// Weight transpose: in fp32 [R,C] -> out half [C,R]
// ---------------------------------------------------------------------------
__global__ void transpose_kernel(const float* __restrict__ in,
                                 __half* __restrict__ out, int R, int C)
{
    __shared__ float t[32][33];
    int bx = blockIdx.x * 32, by = blockIdx.y * 32;
    #pragma unroll
    for (int i = threadIdx.y; i < 32; i += 8)
        t[i][threadIdx.x] = in[(long)(by + i) * C + bx + threadIdx.x];
    __syncthreads();
    #pragma unroll
    for (int i = threadIdx.y; i < 32; i += 8)
        out[(long)(bx + i) * R + by + threadIdx.x] =
            __float2half(t[threadIdx.x][i]);
}

// ---------------------------------------------------------------------------
// fp16 GEMM: C[M,N] = A[M,K] @ Bt[N,K]^T (+ epilogue), fp32 accumulate.
// 128x128 block tile, BK=64 halfs (128B rows, SW128 xor swizzle), 8 warps
// (2m x 4n, warp tile 64x32), ldmatrix.x4 fragments, 3-stage cp.async,
// 96KB smem, 2 CTAs/SM.
// ---------------------------------------------------------------------------
#define EPI_NONE      0     // half out
#define EPI_BIAS_RES  1     // float out: acc + bias + res
#define EPI_GELU_BIAS 2     // half out: gelu(acc + bias)
#define EPI_BIAS_ACC  3     // float out: C += acc + bias

#define BM  128
#define BN  128
#define BKH 64               // halfs per chunk = 128 bytes per row
#define A_BYTES   16384      // 128 rows * 128B
#define STG_BYTES 32768      // A + B
#define STAGES    3
#define GEMM_SMEM_BYTES (STAGES * STG_BYTES)   // 98304

template <int EPI>
__global__ __launch_bounds__(256, 2)
void hgemm(const __half* __restrict__ A, const __half* __restrict__ Bt,
           void* __restrict__ Cv,
           const float* __restrict__ bias,
           const float* __restrict__ res,
           int M, int N, int K)
{
    extern __shared__ char smem[];
    uint32_t sbase = smem_u32(smem);

    int  tid    = threadIdx.x;
    int  lane   = tid & 31;
    int  wid    = tid >> 5;
    int  warp_m = wid >> 2;          // 0..1 (64 rows)
    int  warp_n = wid & 3;           // 0..3 (32 cols)
    long m0     = (long)blockIdx.y * BM;
    int  n0     = blockIdx.x * BN;
    int  nc     = K / BKH;

    int l_row = tid >> 3;            // 0..31 (+32 per it)
    int l_grp = tid & 7;             // 16B group (8 halfs)
    uint32_t l_off = (uint32_t)(l_row * 128 + ((l_grp ^ (l_row & 7)) << 4));

    auto ldgsts = [&](int kc, int st) {
        uint32_t sb = sbase + (uint32_t)st * STG_BYTES + l_off;
        const __half* Ap = A  + (m0 + l_row) * K + kc * BKH + l_grp * 8;
        #pragma unroll
        for (int it = 0; it < 4; it++)
            cpa16(sb + (uint32_t)(it * 32 * 128), Ap + (long)(it * 32) * K);
        const __half* Bp = Bt + ((long)n0 + l_row) * K + kc * BKH + l_grp * 8;
        #pragma unroll
        for (int it = 0; it < 4; it++)
            cpa16(sb + (uint32_t)(A_BYTES + it * 32 * 128),
                  Bp + (long)(it * 32) * K);
        CPA_COMMIT();
    };

    float acc[4][4][4];
    #pragma unroll
    for (int i = 0; i < 4; i++)
        #pragma unroll
        for (int j = 0; j < 4; j++)
            #pragma unroll
            for (int e = 0; e < 4; e++) acc[i][j][e] = 0.f;

    ldgsts(0, 0);
    if (nc > 1) ldgsts(1, 1);

    // ldmatrix lane addressing precompute
    int a_row_l = (lane & 15);           // m offset within 16
    int a_kg_l  = (lane >> 4);           // 0=klo, 1=khi
    int b_row_l = ((lane >> 4) << 3) + (lane & 7);   // n offset within 16
    int b_kg_l  = (lane >> 3) & 1;       // klo/khi

    for (int c = 0; c < nc; c++) {
        if (c + 2 < nc) ldgsts(c + 2, (c + 2) % STAGES);

        int rem = nc - 1 - c; if (rem > 2) rem = 2;
        if (rem == 2)      asm volatile("cp.async.wait_group 2;" ::: "memory");
        else if (rem == 1) asm volatile("cp.async.wait_group 1;" ::: "memory");
        else               asm volatile("cp.async.wait_group 0;" ::: "memory");
        __syncthreads();

        uint32_t smA = sbase + (uint32_t)(c % STAGES) * STG_BYTES;
        uint32_t smB = smA + A_BYTES;

        #pragma unroll
        for (int ks = 0; ks < 4; ks++) {
            uint32_t af[4][4];
            #pragma unroll
            for (int mf = 0; mf < 4; mf++) {
                int row  = warp_m * 64 + mf * 16 + a_row_l;
                int grpk = ks * 2 + a_kg_l;
                uint32_t addr = smA + row * 128 +
                                (((grpk ^ (row & 7)) & 7) << 4);
                ldsm4(af[mf][0], af[mf][1], af[mf][2], af[mf][3], addr);
            }
            uint32_t bf[4][2];
            #pragma unroll
            for (int np = 0; np < 2; np++) {
                int row  = warp_n * 32 + np * 16 + b_row_l;
                int grpk = ks * 2 + b_kg_l;
                uint32_t addr = smB + row * 128 +
                                (((grpk ^ (row & 7)) & 7) << 4);
                uint32_t r0, r1, r2, r3;
                ldsm4(r0, r1, r2, r3, addr);
                bf[np * 2][0]     = r0; bf[np * 2][1]     = r1;
                bf[np * 2 + 1][0] = r2; bf[np * 2 + 1][1] = r3;
            }
            #pragma unroll
            for (int mf = 0; mf < 4; mf++)
                #pragma unroll
                for (int nf = 0; nf < 4; nf++)
                    mma_f16(acc[mf][nf], af[mf], bf[nf]);
        }
        __syncthreads();
    }

    // epilogue: frag rows g, g+8; cols 2q, 2q+1
    int g = lane >> 2;
    int q = lane & 3;

    float2 bv[4];
    if (EPI != EPI_NONE) {
        #pragma unroll
        for (int nf = 0; nf < 4; nf++) {
            int col = n0 + warp_n * 32 + nf * 8 + q * 2;
            bv[nf] = *reinterpret_cast<const float2*>(&bias[col]);
        }
    }

    #pragma unroll
    for (int mf = 0; mf < 4; mf++) {
        long r0 = m0 + warp_m * 64 + mf * 16 + g;
        long r1 = r0 + 8;
        #pragma unroll
        for (int nf = 0; nf < 4; nf++) {
            int col = n0 + warp_n * 32 + nf * 8 + q * 2;
            float2 v0 = make_float2(acc[mf][nf][0], acc[mf][nf][1]);
            float2 v1 = make_float2(acc[mf][nf][2], acc[mf][nf][3]);
            if (EPI == EPI_NONE) {
                __half* C = (__half*)Cv;
                *reinterpret_cast<__half2*>(&C[r0 * N + col]) =
                    __floats2half2_rn(v0.x, v0.y);
                *reinterpret_cast<__half2*>(&C[r1 * N + col]) =
                    __floats2half2_rn(v1.x, v1.y);
            } else if (EPI == EPI_GELU_BIAS) {
                __half* C = (__half*)Cv;
                *reinterpret_cast<__half2*>(&C[r0 * N + col]) =
                    __floats2half2_rn(gelu_exact(v0.x + bv[nf].x),
                                      gelu_exact(v0.y + bv[nf].y));
                *reinterpret_cast<__half2*>(&C[r1 * N + col]) =
                    __floats2half2_rn(gelu_exact(v1.x + bv[nf].x),
                                      gelu_exact(v1.y + bv[nf].y));
            } else if (EPI == EPI_BIAS_RES) {
                float* C = (float*)Cv;
                float2 e0 = *reinterpret_cast<const float2*>(&res[r0 * N + col]);
                float2 e1 = *reinterpret_cast<const float2*>(&res[r1 * N + col]);
                v0.x += bv[nf].x + e0.x; v0.y += bv[nf].y + e0.y;
                v1.x += bv[nf].x + e1.x; v1.y += bv[nf].y + e1.y;
                *reinterpret_cast<float2*>(&C[r0 * N + col]) = v0;
                *reinterpret_cast<float2*>(&C[r1 * N + col]) = v1;
            } else { // EPI_BIAS_ACC
                float* C = (float*)Cv;
                float2 e0 = *reinterpret_cast<const float2*>(&C[r0 * N + col]);
                float2 e1 = *reinterpret_cast<const float2*>(&C[r1 * N + col]);
                v0.x += bv[nf].x + e0.x; v0.y += bv[nf].y + e0.y;
                v1.x += bv[nf].x + e1.x; v1.y += bv[nf].y + e1.y;
                *reinterpret_cast<float2*>(&C[r0 * N + col]) = v0;
                *reinterpret_cast<float2*>(&C[r1 * N + col]) = v1;
            }
        }
    }
}

// ---------------------------------------------------------------------------
// Shifted-window attention: half qkv in, fp32 math, half out.
// One block per (window, head, batch).
// ---------------------------------------------------------------------------
__global__ __launch_bounds__(256)
void attn_kernel(const __half* __restrict__ qkv,
                 const float* __restrict__ pos,
                 __half* __restrict__ out)
{
    int w   = blockIdx.x;
    int h   = blockIdx.y;
    int b   = blockIdx.z;
    int tid = threadIdx.x;

    __shared__ float q[WS][HDIM], k[WS][HDIM], v[WS][HDIM];
    __shared__ float dots[WS][WS + 1];

    // 256 threads = 64 rows x 4 groups of 8 halfs; 3 passes (q,k,v)
    {
        int row = tid >> 2;
        int grp = tid & 3;
        long t = (long)b * NPB + ((w * WS + WS / 2 + row) & (NPB - 1));
        const __half* base = qkv + t * 768 + h * HDIM + grp * 8;
        #pragma unroll
        for (int sel = 0; sel < 3; sel++) {
            uint4 raw = *reinterpret_cast<const uint4*>(base + sel * 256);
            float* dst = (sel == 0) ? &q[row][grp * 8]
                       : (sel == 1) ? &k[row][grp * 8] : &v[row][grp * 8];
            const __half2* hp = reinterpret_cast<const __half2*>(&raw);
            #pragma unroll
            for (int e = 0; e < 4; e++) {
                float2 f = __half22float2(hp[e]);
                dst[2 * e]     = f.x;
                dst[2 * e + 1] = f.y;
            }
        }
    }
    __syncthreads();

    const float scale = 0.17677669529663687f;
    #pragma unroll
    for (int it = 0; it < 16; it++) {
        int e = tid + it * 256;
        int i = e >> 6, j = e & 63;
        float s = 0.f;
        #pragma unroll
        for (int d = 0; d < HDIM; d++) s = fmaf(q[i][d], k[j][d], s);
        dots[i][j] = s * scale + pos[i * WS + j];
    }
    __syncthreads();

    if (tid < WS) {
        float m = -INFINITY;
        #pragma unroll 8
        for (int j = 0; j < WS; j++) m = fmaxf(m, dots[tid][j]);
        float sum = 0.f;
        #pragma unroll 8
        for (int j = 0; j < WS; j++) {
            float e = expf(dots[tid][j] - m);
            dots[tid][j] = e;
            sum += e;
        }
        float inv = 1.f / sum;
        #pragma unroll 8
        for (int j = 0; j < WS; j++) dots[tid][j] *= inv;
    }
    __syncthreads();

    #pragma unroll
    for (int it = 0; it < 8; it++) {
        int e = tid + it * 256;
        int i = e >> 5, d = e & 31;
        float s = 0.f;
        #pragma unroll
        for (int j = 0; j < WS; j++) s = fmaf(dots[i][j], v[j][d], s);
        long t = (long)b * NPB + ((w * WS + WS / 2 + i) & (NPB - 1));
        out[t * DIMC + h * HDIM + d] = __float2half(s);
    }
}

// ---------------------------------------------------------------------------
// launch
// ---------------------------------------------------------------------------
extern "C" void kernel_launch(void* const* d_in, const int* in_sizes, int n_in,
                              void* d_out, int out_size)
{
    const float* x      = (const float*)d_in[0];
    const float* w_qkv  = (const float*)d_in[1];
    const float* w_out  = (const float*)d_in[2];
    const float* b_out  = (const float*)d_in[3];
    const float* pos    = (const float*)d_in[4];
    const float* ln1_g  = (const float*)d_in[5];
    const float* ln1_b  = (const float*)d_in[6];
    const float* w1     = (const float*)d_in[7];
    const float* b1     = (const float*)d_in[8];
    const float* w2     = (const float*)d_in[9];
    const float* b2     = (const float*)d_in[10];
    const float* ln2_g  = (const float*)d_in[11];
    const float* ln2_b  = (const float*)d_in[12];
    float* out = (float*)d_out;

    int tokens = in_sizes[0] / DIMC;   // 131072

    __half *p_ln, *p_qkv, *p_attn, *p_h, *p_wqkvT, *p_woutT, *p_w1T, *p_w2T;
    cudaGetSymbolAddress((void**)&p_ln,    g_ln);
    cudaGetSymbolAddress((void**)&p_qkv,   g_qkv);
    cudaGetSymbolAddress((void**)&p_attn,  g_attn);
    cudaGetSymbolAddress((void**)&p_h,     g_h);
    cudaGetSymbolAddress((void**)&p_wqkvT, g_wqkvT);
    cudaGetSymbolAddress((void**)&p_woutT, g_woutT);
    cudaGetSymbolAddress((void**)&p_w1T,   g_w1T);
    cudaGetSymbolAddress((void**)&p_w2T,   g_w2T);

    cudaFuncSetAttribute(hgemm<EPI_NONE>,
        cudaFuncAttributeMaxDynamicSharedMemorySize, GEMM_SMEM_BYTES);
    cudaFuncSetAttribute(hgemm<EPI_BIAS_RES>,
        cudaFuncAttributeMaxDynamicSharedMemorySize, GEMM_SMEM_BYTES);
    cudaFuncSetAttribute(hgemm<EPI_GELU_BIAS>,
        cudaFuncAttributeMaxDynamicSharedMemorySize, GEMM_SMEM_BYTES);
    cudaFuncSetAttribute(hgemm<EPI_BIAS_ACC>,
        cudaFuncAttributeMaxDynamicSharedMemorySize, GEMM_SMEM_BYTES);

    // transposed half weights [N,K]
    {
        dim3 blk(32, 8);
        transpose_kernel<<<dim3(768 / 32,  DIMC / 32), blk>>>(w_qkv, p_wqkvT, DIMC, 768);
        transpose_kernel<<<dim3(DIMC / 32, DIMC / 32), blk>>>(w_out, p_woutT, DIMC, DIMC);
        transpose_kernel<<<dim3(MLPD / 32, DIMC / 32), blk>>>(w1,    p_w1T,   DIMC, MLPD);
        transpose_kernel<<<dim3(DIMC / 32, MLPD / 32), blk>>>(w2,    p_w2T,   MLPD, DIMC);
    }

    // 1) LN1
    ln_kernel<<<tokens, 256>>>(x, ln1_g, ln1_b, p_ln);

    // 2) QKV = LN1(x) @ w_qkv  (half out)
    {
        dim3 grid(768 / BN, tokens / BM);
        hgemm<EPI_NONE><<<grid, 256, GEMM_SMEM_BYTES>>>(
            p_ln, p_wqkvT, p_qkv, nullptr, nullptr, tokens, 768, DIMC);
    }

    // 3) windowed attention (half out)
    {
        dim3 grid(NPB / WS, HEADS, tokens / NPB);
        attn_kernel<<<grid, 256>>>(p_qkv, pos, p_attn);
    }

    // 4) x2 = x + attn @ w_out + b_out -> d_out (fp32)
    {
        dim3 grid(DIMC / BN, tokens / BM);
        hgemm<EPI_BIAS_RES><<<grid, 256, GEMM_SMEM_BYTES>>>(
            p_attn, p_woutT, out, b_out, x, tokens, DIMC, DIMC);
    }

    // 5) LN2
    ln_kernel<<<tokens, 256>>>(out, ln2_g, ln2_b, p_ln);

    // 6) h = gelu(LN2 @ w1 + b1)  (half out)
    {
        dim3 grid(MLPD / BN, tokens / BM);
        hgemm<EPI_GELU_BIAS><<<grid, 256, GEMM_SMEM_BYTES>>>(
            p_ln, p_w1T, p_h, b1, nullptr, tokens, MLPD, DIMC);
    }

    // 7) out += h @ w2 + b2 (fp32)
    {
        dim3 grid(DIMC / BN, tokens / BM);
        hgemm<EPI_BIAS_ACC><<<grid, 256, GEMM_SMEM_BYTES>>>(
            p_h, p_w2T, out, b2, nullptr, tokens, DIMC, MLPD);
    }
}